// round 1
// baseline (speedup 1.0000x reference)
#include <cuda_runtime.h>
#include <cuda_bf16.h>
#include <cstdint>

#define NUM_USERS 100000
#define NUM_ITEMS 50000
#define N_NODES   150000
#define DIM       64
#define N_LAYERS  3
#define NNZ       4800000
#define NEG_SLOPE 0.01f

#define N_PAD 150016   // padded node count for scratch

// ---------------- static device scratch (no allocations allowed) ----------------
__device__ float g_ego [(size_t)N_PAD * DIM];   // 38.4 MB
__device__ float g_side[(size_t)N_PAD * DIM];   // 38.4 MB
__device__ int   g_counts[N_PAD];
__device__ int   g_rowptr[N_PAD + 1];
__device__ int   g_cursor[N_PAD];
__device__ int2  g_cv[NNZ];                     // (col, val bits) 38.4 MB

// ---------------- init: ego = concat(user,item); out[:,0:64] = ego ----------------
__global__ void k_init(const float* __restrict__ ue, const float* __restrict__ ie,
                       float* __restrict__ out) {
    int idx = blockIdx.x * blockDim.x + threadIdx.x;          // float4 index
    const int total = N_NODES * DIM / 4;                      // 2.4M
    if (idx >= total) return;
    const int uElems = NUM_USERS * DIM / 4;
    float4 v = (idx < uElems) ? ((const float4*)ue)[idx]
                              : ((const float4*)ie)[idx - uElems];
    ((float4*)g_ego)[idx] = v;
    int r  = idx / (DIM / 4);
    int c4 = idx % (DIM / 4);
    ((float4*)(out + (size_t)r * 256))[c4] = v;
}

// ---------------- CSR build ----------------
__global__ void k_zero_counts() {
    int i = blockIdx.x * blockDim.x + threadIdx.x;
    if (i < N_PAD) g_counts[i] = 0;
}

__global__ void k_hist(const int* __restrict__ rows) {
    int e = blockIdx.x * blockDim.x + threadIdx.x;
    if (e < NNZ) atomicAdd(&g_counts[rows[e]], 1);
}

// single-block exclusive scan over counts -> rowptr (+ cursor copy)
__global__ void k_scan() {
    __shared__ int sm[1024];
    __shared__ int carry;
    if (threadIdx.x == 0) carry = 0;
    __syncthreads();
    for (int base = 0; base < N_NODES; base += 1024) {
        int i = base + threadIdx.x;
        int v = (i < N_NODES) ? g_counts[i] : 0;
        sm[threadIdx.x] = v;
        __syncthreads();
        #pragma unroll
        for (int off = 1; off < 1024; off <<= 1) {
            int t = (threadIdx.x >= off) ? sm[threadIdx.x - off] : 0;
            __syncthreads();
            sm[threadIdx.x] += t;
            __syncthreads();
        }
        if (i < N_NODES) {
            int excl = carry + sm[threadIdx.x] - v;
            g_rowptr[i] = excl;
            g_cursor[i] = excl;
        }
        __syncthreads();
        if (threadIdx.x == 0) carry += sm[1023];
        __syncthreads();
    }
    if (threadIdx.x == 0) g_rowptr[N_NODES] = carry;
}

__global__ void k_fill(const int* __restrict__ rows, const int* __restrict__ cols,
                       const float* __restrict__ vals) {
    int e = blockIdx.x * blockDim.x + threadIdx.x;
    if (e >= NNZ) return;
    int r = rows[e];
    int p = atomicAdd(&g_cursor[r], 1);
    g_cv[p] = make_int2(cols[e], __float_as_int(vals[e]));
}

// ---------------- SpMM: warp-per-row gather-sum (atomic-free) ----------------
__global__ void k_spmm() {
    int gwarp = (blockIdx.x * blockDim.x + threadIdx.x) >> 5;
    int lane  = threadIdx.x & 31;
    if (gwarp >= N_NODES) return;
    int beg = g_rowptr[gwarp];
    int end = g_rowptr[gwarp + 1];
    float2 acc = make_float2(0.f, 0.f);
    for (int e = beg; e < end; e++) {
        int2  cv  = g_cv[e];                              // broadcast load
        float val = __int_as_float(cv.y);
        float2 x  = *(const float2*)&g_ego[(size_t)cv.x * DIM + 2 * lane];
        acc.x = fmaf(val, x.x, acc.x);
        acc.y = fmaf(val, x.y, acc.y);
    }
    *(float2*)&g_side[(size_t)gwarp * DIM + 2 * lane] = acc;
}

// ---------------- fused double GEMM: ego=lrelu(side@W1T+b1); mlp=ego@W2T+b2 ----------------
#define GEMM_ROWS 64   // rows per block, 8 warps x 8 rows
__global__ void k_gemm(const float* __restrict__ gcw, const float* __restrict__ gcb,
                       const float* __restrict__ biw, const float* __restrict__ bib,
                       int layer, float* __restrict__ out) {
    __shared__ float sW1[64 * 64];
    __shared__ float sW2[64 * 64];
    __shared__ float sB1[64];
    __shared__ float sB2[64];
    int tid = threadIdx.x;
    const float* w1 = gcw + layer * 4096;
    const float* w2 = biw + layer * 4096;
    for (int idx = tid; idx < 4096; idx += blockDim.x) {
        int j = idx >> 6, k = idx & 63;
        sW1[k * 64 + j] = w1[idx];   // store transposed: sW[k][j]
        sW2[k * 64 + j] = w2[idx];
    }
    if (tid < 64) {
        sB1[tid] = gcb[layer * 64 + tid];
        sB2[tid] = bib[layer * 64 + tid];
    }
    __syncthreads();

    int lane = tid & 31;
    int warp = tid >> 5;
    float2 b1 = *(const float2*)&sB1[2 * lane];
    float2 b2 = *(const float2*)&sB2[2 * lane];
    int rbase = blockIdx.x * GEMM_ROWS;

    for (int rr = warp; rr < GEMM_ROWS; rr += 8) {
        int r = rbase + rr;
        if (r >= N_NODES) break;                    // uniform per warp
        float2 sv = *(const float2*)&g_side[(size_t)r * DIM + 2 * lane];
        float2 acc = make_float2(0.f, 0.f);
        #pragma unroll
        for (int k = 0; k < 64; k++) {
            float s = __shfl_sync(0xffffffffu, (k & 1) ? sv.y : sv.x, k >> 1);
            float2 w = *(const float2*)&sW1[k * 64 + 2 * lane];
            acc.x = fmaf(s, w.x, acc.x);
            acc.y = fmaf(s, w.y, acc.y);
        }
        acc.x += b1.x; acc.y += b1.y;
        acc.x = (acc.x > 0.f) ? acc.x : NEG_SLOPE * acc.x;
        acc.y = (acc.y > 0.f) ? acc.y : NEG_SLOPE * acc.y;
        *(float2*)&g_ego[(size_t)r * DIM + 2 * lane] = acc;   // new ego (next layer input)

        float2 m = make_float2(0.f, 0.f);
        #pragma unroll
        for (int k = 0; k < 64; k++) {
            float s = __shfl_sync(0xffffffffu, (k & 1) ? acc.y : acc.x, k >> 1);
            float2 w = *(const float2*)&sW2[k * 64 + 2 * lane];
            m.x = fmaf(s, w.x, m.x);
            m.y = fmaf(s, w.y, m.y);
        }
        m.x += b2.x; m.y += b2.y;
        *(float2*)&out[(size_t)r * 256 + (size_t)(layer + 1) * 64 + 2 * lane] = m;
    }
}

// ---------------- launch ----------------
extern "C" void kernel_launch(void* const* d_in, const int* in_sizes, int n_in,
                              void* d_out, int out_size) {
    const float* ue  = (const float*)d_in[0];
    const float* ie  = (const float*)d_in[1];
    const float* gcw = (const float*)d_in[2];
    const float* gcb = (const float*)d_in[3];
    const float* biw = (const float*)d_in[4];
    const float* bib = (const float*)d_in[5];
    const int*   er  = (const int*)d_in[6];
    const int*   ec  = (const int*)d_in[7];
    const float* ev  = (const float*)d_in[8];
    float* out = (float*)d_out;

    // init ego + out[:,0:64]
    k_init<<<(N_NODES * DIM / 4 + 255) / 256, 256>>>(ue, ie, out);

    // CSR build (once per replay, used by all 3 layers)
    k_zero_counts<<<(N_PAD + 255) / 256, 256>>>();
    k_hist<<<NNZ / 256, 256>>>(er);
    k_scan<<<1, 1024>>>();
    k_fill<<<NNZ / 256, 256>>>(er, ec, ev);

    for (int layer = 0; layer < N_LAYERS; layer++) {
        k_spmm<<<(N_NODES + 7) / 8, 256>>>();
        k_gemm<<<(N_NODES + GEMM_ROWS - 1) / GEMM_ROWS, 256>>>(gcw, gcb, biw, bib, layer, out);
    }
}

// round 2
// speedup vs baseline: 1.1354x; 1.1354x over previous
#include <cuda_runtime.h>
#include <cuda_bf16.h>
#include <cstdint>

#define NUM_USERS 100000
#define NUM_ITEMS 50000
#define N_NODES   150000
#define DIM       64
#define N_LAYERS  3
#define NNZ       4800000
#define NEG_SLOPE 0.01f

#define N_PAD 150016
#define SCAN_NBLK 147          // 147 * 1024 = 150528 >= N_NODES

// ---------------- static device scratch ----------------
__device__ float g_ego [(size_t)N_PAD * DIM];
__device__ float g_side[(size_t)N_PAD * DIM];
__device__ int   g_counts[N_PAD];
__device__ int   g_rowptr[N_PAD + 1];
__device__ int   g_cursor[N_PAD];
__device__ int2  g_cv[NNZ];
__device__ int   g_bsum[SCAN_NBLK];
__device__ int   g_boff[SCAN_NBLK];

// ---------------- f32x2 helpers ----------------
__device__ __forceinline__ unsigned long long pack2(float x, float y) {
    unsigned long long r;
    asm("mov.b64 %0, {%1, %2};" : "=l"(r) : "f"(x), "f"(y));
    return r;
}
__device__ __forceinline__ void unpack2(unsigned long long v, float& x, float& y) {
    asm("mov.b64 {%0, %1}, %2;" : "=f"(x), "=f"(y) : "l"(v));
}
__device__ __forceinline__ void fma2(unsigned long long& d,
                                     unsigned long long a, unsigned long long b) {
    asm("fma.rn.f32x2 %0, %1, %2, %0;" : "+l"(d) : "l"(a), "l"(b));
}

// ---------------- init: ego = concat(user,item); out[:,0:64] = ego ----------------
__global__ void k_init(const float* __restrict__ ue, const float* __restrict__ ie,
                       float* __restrict__ out) {
    int idx = blockIdx.x * blockDim.x + threadIdx.x;
    const int total = N_NODES * DIM / 4;
    if (idx >= total) return;
    const int uElems = NUM_USERS * DIM / 4;
    float4 v = (idx < uElems) ? ((const float4*)ue)[idx]
                              : ((const float4*)ie)[idx - uElems];
    ((float4*)g_ego)[idx] = v;
    int r  = idx / (DIM / 4);
    int c4 = idx % (DIM / 4);
    ((float4*)(out + (size_t)r * 256))[c4] = v;
}

// ---------------- CSR build ----------------
__global__ void k_zero_counts() {
    int i = blockIdx.x * blockDim.x + threadIdx.x;
    if (i < N_PAD) g_counts[i] = 0;
}

__global__ void k_hist(const int* __restrict__ rows) {
    int e = blockIdx.x * blockDim.x + threadIdx.x;
    if (e < NNZ) atomicAdd(&g_counts[rows[e]], 1);
}

// block-level exclusive scan of 1024 elements (warp shuffle + smem)
__device__ __forceinline__ int block_excl_scan_1024(int v, int tid, int* warp_sums) {
    int lane = tid & 31, warp = tid >> 5;
    // inclusive warp scan
    int x = v;
    #pragma unroll
    for (int off = 1; off < 32; off <<= 1) {
        int t = __shfl_up_sync(0xffffffffu, x, off);
        if (lane >= off) x += t;
    }
    if (lane == 31) warp_sums[warp] = x;
    __syncthreads();
    if (warp == 0) {
        int w = warp_sums[lane];
        int y = w;
        #pragma unroll
        for (int off = 1; off < 32; off <<= 1) {
            int t = __shfl_up_sync(0xffffffffu, y, off);
            if (lane >= off) y += t;
        }
        warp_sums[lane] = y - w;   // exclusive warp offsets
    }
    __syncthreads();
    return warp_sums[warp] + x - v;   // exclusive
}

// pass 1: local exclusive scan within each 1024-block; block sum to g_bsum
__global__ void k_scan1() {
    __shared__ int warp_sums[32];
    __shared__ int blk_total[1];
    int tid = threadIdx.x;
    int i = blockIdx.x * 1024 + tid;
    int v = (i < N_NODES) ? g_counts[i] : 0;
    int excl = block_excl_scan_1024(v, tid, warp_sums);
    if (tid == 1023) blk_total[0] = excl + v;
    if (i < N_NODES) g_rowptr[i] = excl;      // local (no global offset yet)
    __syncthreads();
    if (tid == 0) g_bsum[blockIdx.x] = blk_total[0];
}

// pass 2: single block scans the 147 block sums
__global__ void k_scan2() {
    __shared__ int sm[256];
    int tid = threadIdx.x;
    int v = (tid < SCAN_NBLK) ? g_bsum[tid] : 0;
    sm[tid] = v;
    __syncthreads();
    #pragma unroll
    for (int off = 1; off < 256; off <<= 1) {
        int t = (tid >= off) ? sm[tid - off] : 0;
        __syncthreads();
        sm[tid] += t;
        __syncthreads();
    }
    if (tid < SCAN_NBLK) g_boff[tid] = sm[tid] - v;   // exclusive
    if (tid == 255) g_rowptr[N_NODES] = sm[255];      // == NNZ
}

// pass 3: add block offsets; init cursor
__global__ void k_scan3() {
    int i = blockIdx.x * 1024 + threadIdx.x;
    if (i >= N_NODES) return;
    int r = g_rowptr[i] + g_boff[blockIdx.x];
    g_rowptr[i] = r;
    g_cursor[i] = r;
}

__global__ void k_fill(const int* __restrict__ rows, const int* __restrict__ cols,
                       const float* __restrict__ vals) {
    int e = blockIdx.x * blockDim.x + threadIdx.x;
    if (e >= NNZ) return;
    int r = rows[e];
    int p = atomicAdd(&g_cursor[r], 1);
    g_cv[p] = make_int2(cols[e], __float_as_int(vals[e]));
}

// ---------------- SpMM: warp-per-row gather-sum, 2-way unrolled ----------------
__global__ void k_spmm() {
    int gwarp = (blockIdx.x * blockDim.x + threadIdx.x) >> 5;
    int lane  = threadIdx.x & 31;
    if (gwarp >= N_NODES) return;
    int beg = g_rowptr[gwarp];
    int end = g_rowptr[gwarp + 1];
    float2 a0 = make_float2(0.f, 0.f);
    float2 a1 = make_float2(0.f, 0.f);
    int e = beg;
    for (; e + 1 < end; e += 2) {
        int2 cv0 = g_cv[e];
        int2 cv1 = g_cv[e + 1];
        float2 x0 = *(const float2*)&g_ego[(size_t)cv0.x * DIM + 2 * lane];
        float2 x1 = *(const float2*)&g_ego[(size_t)cv1.x * DIM + 2 * lane];
        float v0 = __int_as_float(cv0.y);
        float v1 = __int_as_float(cv1.y);
        a0.x = fmaf(v0, x0.x, a0.x);
        a0.y = fmaf(v0, x0.y, a0.y);
        a1.x = fmaf(v1, x1.x, a1.x);
        a1.y = fmaf(v1, x1.y, a1.y);
    }
    if (e < end) {
        int2 cv = g_cv[e];
        float2 x = *(const float2*)&g_ego[(size_t)cv.x * DIM + 2 * lane];
        float v = __int_as_float(cv.y);
        a0.x = fmaf(v, x.x, a0.x);
        a0.y = fmaf(v, x.y, a0.y);
    }
    a0.x += a1.x; a0.y += a1.y;
    *(float2*)&g_side[(size_t)gwarp * DIM + 2 * lane] = a0;
}

// ---------------- fused double GEMM with packed f32x2 ----------------
#define GEMM_ROWS 64   // 8 warps x 8 rows
__global__ void k_gemm(const float* __restrict__ gcw, const float* __restrict__ gcb,
                       const float* __restrict__ biw, const float* __restrict__ bib,
                       int layer, float* __restrict__ out) {
    __shared__ float sW1[64 * 64];
    __shared__ float sW2[64 * 64];
    __shared__ float sB1[64];
    __shared__ float sB2[64];
    __shared__ float2 sDup[8][64];   // per warp: duplicated (s,s) side values
    int tid = threadIdx.x;
    const float* w1 = gcw + layer * 4096;
    const float* w2 = biw + layer * 4096;
    for (int idx = tid; idx < 4096; idx += blockDim.x) {
        int j = idx >> 6, k = idx & 63;
        sW1[k * 64 + j] = w1[idx];   // transposed: sW[k][j]
        sW2[k * 64 + j] = w2[idx];
    }
    if (tid < 64) {
        sB1[tid] = gcb[layer * 64 + tid];
        sB2[tid] = bib[layer * 64 + tid];
    }
    __syncthreads();

    int lane = tid & 31;
    int warp = tid >> 5;
    float2 b1 = *(const float2*)&sB1[2 * lane];
    float2 b2 = *(const float2*)&sB2[2 * lane];
    int rbase = blockIdx.x * GEMM_ROWS;

    for (int rr = warp; rr < GEMM_ROWS; rr += 8) {
        int r = rbase + rr;
        if (r >= N_NODES) break;
        float2 sv = *(const float2*)&g_side[(size_t)r * DIM + 2 * lane];
        sDup[warp][2 * lane]     = make_float2(sv.x, sv.x);
        sDup[warp][2 * lane + 1] = make_float2(sv.y, sv.y);
        __syncwarp();

        unsigned long long acc = 0ULL;   // (0.f, 0.f)
        #pragma unroll
        for (int k = 0; k < 64; k++) {
            unsigned long long s2 = *(const unsigned long long*)&sDup[warp][k];
            unsigned long long w2v = *(const unsigned long long*)&sW1[k * 64 + 2 * lane];
            fma2(acc, s2, w2v);
        }
        float ex, ey;
        unpack2(acc, ex, ey);
        ex += b1.x; ey += b1.y;
        ex = (ex > 0.f) ? ex : NEG_SLOPE * ex;
        ey = (ey > 0.f) ? ey : NEG_SLOPE * ey;
        *(float2*)&g_ego[(size_t)r * DIM + 2 * lane] = make_float2(ex, ey);

        __syncwarp();   // all reads of sDup done before overwrite
        sDup[warp][2 * lane]     = make_float2(ex, ex);
        sDup[warp][2 * lane + 1] = make_float2(ey, ey);
        __syncwarp();

        unsigned long long macc = 0ULL;
        #pragma unroll
        for (int k = 0; k < 64; k++) {
            unsigned long long s2 = *(const unsigned long long*)&sDup[warp][k];
            unsigned long long w2v = *(const unsigned long long*)&sW2[k * 64 + 2 * lane];
            fma2(macc, s2, w2v);
        }
        float mx, my;
        unpack2(macc, mx, my);
        mx += b2.x; my += b2.y;
        *(float2*)&out[(size_t)r * 256 + (size_t)(layer + 1) * 64 + 2 * lane]
            = make_float2(mx, my);
        __syncwarp();   // protect sDup before next row's overwrite
    }
}

// ---------------- launch ----------------
extern "C" void kernel_launch(void* const* d_in, const int* in_sizes, int n_in,
                              void* d_out, int out_size) {
    const float* ue  = (const float*)d_in[0];
    const float* ie  = (const float*)d_in[1];
    const float* gcw = (const float*)d_in[2];
    const float* gcb = (const float*)d_in[3];
    const float* biw = (const float*)d_in[4];
    const float* bib = (const float*)d_in[5];
    const int*   er  = (const int*)d_in[6];
    const int*   ec  = (const int*)d_in[7];
    const float* ev  = (const float*)d_in[8];
    float* out = (float*)d_out;

    k_init<<<(N_NODES * DIM / 4 + 255) / 256, 256>>>(ue, ie, out);

    k_zero_counts<<<(N_PAD + 255) / 256, 256>>>();
    k_hist<<<NNZ / 256, 256>>>(er);
    k_scan1<<<SCAN_NBLK, 1024>>>();
    k_scan2<<<1, 256>>>();
    k_scan3<<<SCAN_NBLK, 1024>>>();
    k_fill<<<NNZ / 256, 256>>>(er, ec, ev);

    for (int layer = 0; layer < N_LAYERS; layer++) {
        k_spmm<<<(N_NODES + 7) / 8, 256>>>();
        k_gemm<<<(N_NODES + GEMM_ROWS - 1) / GEMM_ROWS, 256>>>(gcw, gcb, biw, bib, layer, out);
    }
}